// round 1
// baseline (speedup 1.0000x reference)
#include <cuda_runtime.h>
#include <cuda_bf16.h>
#include <math.h>

// Problem constants
#define BB    2
#define LQ_   2048
#define LK_   2048
#define EE    1024
#define HH    16
#define DKK   64
#define DVV   64
#define TOPK_ 64

// Device scratch (allocation-free rule: static __device__ arrays)
__device__ __align__(256) float g_qp[BB*HH*LQ_*DKK];          // [b,h,q,d]  16MB
__device__ __align__(256) float g_kp[BB*HH*LK_*DKK];          // [b,h,k,d]  16MB
__device__ __align__(256) float g_vp[BB*HH*LK_*DVV];          // [b,h,k,d]  16MB
__device__ __align__(256) float g_mix[BB*LQ_*HH*DVV];         // [b,q,h,d]  16MB
__device__ __align__(256) float g_logits[(size_t)BB*HH*LQ_*LK_]; // 512MB

// ---------------------------------------------------------------------------
// C = A * W^T.  A: [M,K] row-major, W: [N,K] row-major. K % 32 == 0,
// M % 64 == 0, N % 64 == 0.  mode 0: scatter to [(b*nH+h)*Lrows + l]*64 + d
// layout (n = h*64+d, m = b*Lrows + l).  mode 1: plain row-major [M,N].
// Batched via blockIdx.z with element strides sA/sW/sC.
// ---------------------------------------------------------------------------
__global__ __launch_bounds__(256) void sgemm_nt(
    const float* __restrict__ A, const float* __restrict__ W, float* __restrict__ C,
    int M, int N, int K, int mode, float scale, int Lrows,
    size_t sA, size_t sW, size_t sC)
{
    A += (size_t)blockIdx.z * sA;
    W += (size_t)blockIdx.z * sW;
    C += (size_t)blockIdx.z * sC;
    const int m0 = blockIdx.y * 64;
    const int n0 = blockIdx.x * 64;
    const int tid = threadIdx.x;
    const int ty = tid >> 4;    // 0..15 -> m micro-row group
    const int tx = tid & 15;    // 0..15 -> n micro-col group

    __shared__ __align__(16) float As[32][68];
    __shared__ __align__(16) float Ws[32][68];

    float acc[4][4];
    #pragma unroll
    for (int i = 0; i < 4; i++)
        #pragma unroll
        for (int j = 0; j < 4; j++) acc[i][j] = 0.f;

    for (int kt = 0; kt < K; kt += 32) {
        #pragma unroll
        for (int i = 0; i < 2; i++) {
            int f  = tid + i * 256;     // 0..511 float4 slots
            int r  = f >> 3;            // row 0..63
            int c4 = (f & 7) << 2;      // k offset 0..28
            float4 a = *(const float4*)(A + (size_t)(m0 + r) * K + kt + c4);
            As[c4+0][r] = a.x; As[c4+1][r] = a.y; As[c4+2][r] = a.z; As[c4+3][r] = a.w;
            float4 w = *(const float4*)(W + (size_t)(n0 + r) * K + kt + c4);
            Ws[c4+0][r] = w.x; Ws[c4+1][r] = w.y; Ws[c4+2][r] = w.z; Ws[c4+3][r] = w.w;
        }
        __syncthreads();
        #pragma unroll
        for (int e = 0; e < 32; e++) {
            float4 ra = *(const float4*)&As[e][ty << 2];
            float4 rb = *(const float4*)&Ws[e][tx << 2];
            float av[4] = {ra.x, ra.y, ra.z, ra.w};
            float bv[4] = {rb.x, rb.y, rb.z, rb.w};
            #pragma unroll
            for (int i = 0; i < 4; i++)
                #pragma unroll
                for (int j = 0; j < 4; j++)
                    acc[i][j] += av[i] * bv[j];
        }
        __syncthreads();
    }

    const int nH = N >> 6;
    #pragma unroll
    for (int i = 0; i < 4; i++) {
        int m = m0 + (ty << 2) + i;
        #pragma unroll
        for (int j = 0; j < 4; j++) {
            int n = n0 + (tx << 2) + j;
            float val = acc[i][j] * scale;
            if (mode == 0) {
                int b = m / Lrows, l = m - b * Lrows;
                int h = n >> 6, d = n & 63;
                C[(((size_t)b * nH + h) * Lrows + l) * 64 + d] = val;
            } else {
                C[(size_t)m * N + n] = val;
            }
        }
    }
}

// ---------------------------------------------------------------------------
// Per-row: top-64 selection (radix select on order-preserving uint, ties ->
// lowest index, matching jax.lax.top_k), softmax over the 64 kept logits,
// sparse AV into g_mix, optional full attn row write.
// One CTA of 128 threads per (b,h,q) row.  Deterministic reductions.
// ---------------------------------------------------------------------------
__global__ __launch_bounds__(128) void topk_attn_kernel(
    const float* __restrict__ logits, const float* __restrict__ vp,
    float* __restrict__ mix, float* __restrict__ attn, int write_attn)
{
    const int row = blockIdx.x;          // bh*LQ + q
    const int bh  = row >> 11;           // row / 2048
    const int qi  = row & 2047;
    const int b   = bh >> 4;
    const int h   = bh & 15;
    const int tid = threadIdx.x;

    __shared__ float         sl[LK_];
    __shared__ unsigned      su[LK_];
    __shared__ unsigned char flags[LK_];
    __shared__ int           hist[256];
    __shared__ float         sred[128];
    __shared__ int           scnt[128];
    __shared__ int           sel_idx[TOPK_];
    __shared__ float         sel_l[TOPK_];
    __shared__ float         sel_w[TOPK_];
    __shared__ unsigned      s_prefix;
    __shared__ int           s_k;

    // Load row, build order-preserving keys, local max
    const float* lrow = logits + (size_t)row * LK_;
    float lm = -INFINITY;
    for (int i = tid; i < LK_; i += 128) {
        float x = lrow[i];
        sl[i] = x;
        unsigned ub = __float_as_uint(x);
        su[i] = (ub & 0x80000000u) ? ~ub : (ub | 0x80000000u);
        lm = fmaxf(lm, x);
    }
    sred[tid] = lm;
    if (tid == 0) { s_prefix = 0u; s_k = TOPK_; }
    __syncthreads();
    for (int off = 64; off > 0; off >>= 1) {
        if (tid < off) sred[tid] = fmaxf(sred[tid], sred[tid + off]);
        __syncthreads();
    }
    const float rowmax = sred[0];
    __syncthreads();

    // Radix select: value of the 64th largest key (8-bit digits, MSB first)
    unsigned pmask = 0u;
    for (int shift = 24; shift >= 0; shift -= 8) {
        hist[tid] = 0; hist[tid + 128] = 0;
        __syncthreads();
        unsigned pref = s_prefix;
        for (int i = tid; i < LK_; i += 128) {
            unsigned u = su[i];
            if ((u & pmask) == pref) atomicAdd(&hist[(u >> shift) & 255], 1);
        }
        __syncthreads();
        if (tid == 0) {
            int kk = s_k; int dsel = 0;
            for (int dgt = 255; dgt >= 0; dgt--) {
                int c = hist[dgt];
                if (kk <= c) { dsel = dgt; break; }
                kk -= c;
            }
            s_k = kk;
            s_prefix = pref | ((unsigned)dsel << shift);
        }
        __syncthreads();
        pmask |= (0xffu << shift);
    }
    const unsigned uT  = s_prefix;
    const int      kfin = s_k;   // number of ==threshold elems to keep (lowest idx)

    for (int i = tid; i < LK_; i += 128) flags[i] = (su[i] > uT) ? 1 : 0;
    __syncthreads();
    if (tid == 0) {  // tie resolution in index order (jax top_k semantics)
        int need = kfin;
        for (int i = 0; i < LK_ && need > 0; i++)
            if (su[i] == uT) { flags[i] = 1; need--; }
    }
    __syncthreads();

    // Deterministic softmax denominator + compaction counts (blocked ownership)
    const int base = tid * 16;
    float zl = 0.f;
    int cnt = 0;
    #pragma unroll 4
    for (int j = 0; j < 16; j++) {
        int i = base + j;
        if (flags[i]) { zl += expf(sl[i] - rowmax); cnt++; }
    }
    sred[tid] = zl; scnt[tid] = cnt;
    __syncthreads();
    for (int off = 64; off > 0; off >>= 1) {
        if (tid < off) sred[tid] += sred[tid + off];
        __syncthreads();
    }
    const float invZ = 1.0f / sred[0];
    if (tid == 0) {
        int run = 0;
        for (int t = 0; t < 128; t++) { int c = scnt[t]; scnt[t] = run; run += c; }
    }
    __syncthreads();
    int pos = scnt[tid];
    for (int j = 0; j < 16; j++) {
        int i = base + j;
        if (flags[i]) { sel_idx[pos] = i; sel_l[pos] = sl[i]; pos++; }
    }
    __syncthreads();
    if (tid < TOPK_) sel_w[tid] = expf(sel_l[tid] - rowmax) * invZ;
    __syncthreads();

    // Sparse AV: out[d] = sum_s w_s * vp[bh, sel_idx[s], d]
    {
        const int d = tid & 63, half = tid >> 6;
        float accv = 0.f;
        const float* vb = vp + (size_t)bh * LK_ * 64;
        for (int s = half; s < TOPK_; s += 2)
            accv += sel_w[s] * vb[(size_t)sel_idx[s] * 64 + d];
        __syncthreads();
        sred[tid] = accv;
        __syncthreads();
        if (tid < 64)
            mix[((size_t)(b * LQ_ + qi)) * (HH * DVV) + h * 64 + tid] =
                sred[tid] + sred[tid + 64];
    }

    // Full attn row (exact zeros at non-selected, matching masked softmax)
    if (write_attn) {
        float* arow = attn + (size_t)row * LK_;
        for (int i = tid; i < LK_; i += 128)
            arow[i] = flags[i] ? expf(sl[i] - rowmax) * invZ : 0.f;
    }
}

// ---------------------------------------------------------------------------
extern "C" void kernel_launch(void* const* d_in, const int* in_sizes, int n_in,
                              void* d_out, int out_size) {
    (void)in_sizes; (void)n_in;
    const float* q    = (const float*)d_in[0];
    const float* k    = (const float*)d_in[1];
    const float* v    = (const float*)d_in[2];
    const float* w_qs = (const float*)d_in[3];
    const float* w_ks = (const float*)d_in[4];
    const float* w_vs = (const float*)d_in[5];
    const float* fc   = (const float*)d_in[6];
    float* out = (float*)d_out;

    float *qp, *kp, *vp, *mix, *lg;
    cudaGetSymbolAddress((void**)&qp,  g_qp);
    cudaGetSymbolAddress((void**)&kp,  g_kp);
    cudaGetSymbolAddress((void**)&vp,  g_vp);
    cudaGetSymbolAddress((void**)&mix, g_mix);
    cudaGetSymbolAddress((void**)&lg,  g_logits);

    dim3 blk(256);
    // QP = (q @ w_qs^T) * 0.125  (exact power-of-2 scale folded in)
    sgemm_nt<<<dim3(16, 64, 1), blk>>>(q, w_qs, qp, BB*LQ_, HH*DKK, EE, 0, 0.125f, LQ_, 0, 0, 0);
    // KP = k @ w_ks^T
    sgemm_nt<<<dim3(16, 64, 1), blk>>>(k, w_ks, kp, BB*LK_, HH*DKK, EE, 0, 1.0f, LK_, 0, 0, 0);
    // VP = v @ w_vs^T
    sgemm_nt<<<dim3(16, 64, 1), blk>>>(v, w_vs, vp, BB*LK_, HH*DVV, DVV, 0, 1.0f, LK_, 0, 0, 0);
    // logits[bh] = QP[bh] @ KP[bh]^T   (batched over 32 bh planes)
    sgemm_nt<<<dim3(32, 32, BB*HH), blk>>>(qp, kp, lg, LQ_, LK_, DKK, 1, 1.0f, 0,
                                           (size_t)LQ_ * DKK, (size_t)LK_ * DKK,
                                           (size_t)LQ_ * LK_);
    // Decide whether the harness checks the flattened (out, attn) tuple
    const long long out_elems  = (long long)BB * LQ_ * DVV;              // 262144
    const long long attn_elems = (long long)BB * HH * LQ_ * LK_;         // 134217728
    int write_attn = ((long long)out_size >= out_elems + attn_elems) ? 1 : 0;

    topk_attn_kernel<<<BB * HH * LQ_, 128>>>(lg, vp, mix, out + out_elems, write_attn);

    // out = mix @ fc^T  -> first 262144 elements of d_out
    sgemm_nt<<<dim3(1, 64, 1), blk>>>(mix, fc, out, BB*LQ_, DVV, HH*DVV, 1, 1.0f, 0, 0, 0, 0);
}

// round 2
// speedup vs baseline: 1.0613x; 1.0613x over previous
#include <cuda_runtime.h>
#include <cuda_bf16.h>
#include <math.h>

// Problem constants
#define BB    2
#define LQ_   2048
#define LK_   2048
#define EE    1024
#define HH    16
#define DKK   64
#define DVV   64
#define TOPK_ 64

// Device scratch (allocation-free rule: static __device__ arrays)
__device__ __align__(256) float g_qp[BB*HH*LQ_*DKK];          // 16MB
__device__ __align__(256) float g_kp[BB*HH*LK_*DKK];          // 16MB
__device__ __align__(256) float g_vp[BB*HH*LK_*DVV];          // 16MB
__device__ __align__(256) float g_mix[BB*LQ_*HH*DVV];         // 16MB
__device__ __align__(256) float g_logits[(size_t)BB*HH*LQ_*LK_]; // 512MB

// ---------------------------------------------------------------------------
// Small-N GEMM kept for fc (N=64): C = A*W^T, 64x64 tile, 4x4 micro.
// ---------------------------------------------------------------------------
__global__ __launch_bounds__(256) void sgemm_nt(
    const float* __restrict__ A, const float* __restrict__ W, float* __restrict__ C,
    int M, int N, int K, float scale)
{
    const int m0 = blockIdx.y * 64;
    const int n0 = blockIdx.x * 64;
    const int tid = threadIdx.x;
    const int ty = tid >> 4;
    const int tx = tid & 15;

    __shared__ __align__(16) float As[32][68];
    __shared__ __align__(16) float Ws[32][68];

    float acc[4][4];
    #pragma unroll
    for (int i = 0; i < 4; i++)
        #pragma unroll
        for (int j = 0; j < 4; j++) acc[i][j] = 0.f;

    for (int kt = 0; kt < K; kt += 32) {
        #pragma unroll
        for (int i = 0; i < 2; i++) {
            int f  = tid + i * 256;
            int r  = f >> 3;
            int c4 = (f & 7) << 2;
            float4 a = *(const float4*)(A + (size_t)(m0 + r) * K + kt + c4);
            As[c4+0][r] = a.x; As[c4+1][r] = a.y; As[c4+2][r] = a.z; As[c4+3][r] = a.w;
            float4 w = *(const float4*)(W + (size_t)(n0 + r) * K + kt + c4);
            Ws[c4+0][r] = w.x; Ws[c4+1][r] = w.y; Ws[c4+2][r] = w.z; Ws[c4+3][r] = w.w;
        }
        __syncthreads();
        #pragma unroll
        for (int e = 0; e < 32; e++) {
            float4 ra = *(const float4*)&As[e][ty << 2];
            float4 rb = *(const float4*)&Ws[e][tx << 2];
            float av[4] = {ra.x, ra.y, ra.z, ra.w};
            float bv[4] = {rb.x, rb.y, rb.z, rb.w};
            #pragma unroll
            for (int i = 0; i < 4; i++)
                #pragma unroll
                for (int j = 0; j < 4; j++)
                    acc[i][j] += av[i] * bv[j];
        }
        __syncthreads();
    }
    #pragma unroll
    for (int i = 0; i < 4; i++) {
        int m = m0 + (ty << 2) + i;
        #pragma unroll
        for (int j = 0; j < 4; j++) {
            int n = n0 + (tx << 2) + j;
            C[(size_t)m * N + n] = acc[i][j] * scale;
        }
    }
}

// ---------------------------------------------------------------------------
// 128x128 tile, 8x8 micro-tile SGEMM: C = A * W^T.  A:[M,K], W:[N,K] row-major.
// K%16==0, M%128==0, N%128==0.
// mode 0: scatter n=(h*64+d), m=(b*Lrows+l) -> [(b*nH+h)*Lrows+l]*64+d
// mode 1: row-major [M,N].  Batched via blockIdx.z.
// ---------------------------------------------------------------------------
__global__ __launch_bounds__(256) void sgemm128(
    const float* __restrict__ A, const float* __restrict__ W, float* __restrict__ C,
    int M, int N, int K, int mode, float scale, int Lrows,
    size_t sA, size_t sW, size_t sC)
{
    A += (size_t)blockIdx.z * sA;
    W += (size_t)blockIdx.z * sW;
    C += (size_t)blockIdx.z * sC;
    const int m0 = blockIdx.y * 128;
    const int n0 = blockIdx.x * 128;
    const int tid = threadIdx.x;
    const int ty = tid >> 4;     // 0..15
    const int tx = tid & 15;     // 0..15

    __shared__ __align__(16) float As[16][132];
    __shared__ __align__(16) float Ws[16][132];

    float acc[8][8];
    #pragma unroll
    for (int i = 0; i < 8; i++)
        #pragma unroll
        for (int j = 0; j < 8; j++) acc[i][j] = 0.f;

    for (int kt = 0; kt < K; kt += 16) {
        #pragma unroll
        for (int i = 0; i < 2; i++) {
            int f  = tid + i * 256;     // 0..511
            int r  = f >> 2;            // row 0..127
            int c4 = (f & 3) << 2;      // k offset 0,4,8,12
            float4 a = *(const float4*)(A + (size_t)(m0 + r) * K + kt + c4);
            As[c4+0][r] = a.x; As[c4+1][r] = a.y; As[c4+2][r] = a.z; As[c4+3][r] = a.w;
            float4 w = *(const float4*)(W + (size_t)(n0 + r) * K + kt + c4);
            Ws[c4+0][r] = w.x; Ws[c4+1][r] = w.y; Ws[c4+2][r] = w.z; Ws[c4+3][r] = w.w;
        }
        __syncthreads();
        #pragma unroll
        for (int e = 0; e < 16; e++) {
            float4 a0 = *(const float4*)&As[e][ty * 8];
            float4 a1 = *(const float4*)&As[e][ty * 8 + 4];
            float4 b0 = *(const float4*)&Ws[e][tx * 8];
            float4 b1 = *(const float4*)&Ws[e][tx * 8 + 4];
            float av[8] = {a0.x, a0.y, a0.z, a0.w, a1.x, a1.y, a1.z, a1.w};
            float bv[8] = {b0.x, b0.y, b0.z, b0.w, b1.x, b1.y, b1.z, b1.w};
            #pragma unroll
            for (int i = 0; i < 8; i++)
                #pragma unroll
                for (int j = 0; j < 8; j++)
                    acc[i][j] += av[i] * bv[j];
        }
        __syncthreads();
    }

    const int nH = N >> 6;
    #pragma unroll
    for (int i = 0; i < 8; i++) {
        int m = m0 + ty * 8 + i;
        if (mode == 0) {
            int b = m / Lrows, l = m - b * Lrows;
            #pragma unroll
            for (int j2 = 0; j2 < 2; j2++) {
                int n = n0 + tx * 8 + j2 * 4;
                int h = n >> 6, d = n & 63;
                float4 o = make_float4(acc[i][j2*4+0]*scale, acc[i][j2*4+1]*scale,
                                       acc[i][j2*4+2]*scale, acc[i][j2*4+3]*scale);
                *(float4*)&C[(((size_t)b * nH + h) * Lrows + l) * 64 + d] = o;
            }
        } else {
            #pragma unroll
            for (int j2 = 0; j2 < 2; j2++) {
                int n = n0 + tx * 8 + j2 * 4;
                float4 o = make_float4(acc[i][j2*4+0]*scale, acc[i][j2*4+1]*scale,
                                       acc[i][j2*4+2]*scale, acc[i][j2*4+3]*scale);
                *(float4*)&C[(size_t)m * N + n] = o;
            }
        }
    }
}

// ---------------------------------------------------------------------------
// Top-k + softmax + sparse AV, fully parallel (no serial tid==0 loops).
// ---------------------------------------------------------------------------
__device__ __forceinline__ unsigned encf(float x) {
    unsigned u = __float_as_uint(x);
    return (u & 0x80000000u) ? ~u : (u | 0x80000000u);
}
__device__ __forceinline__ float decf(unsigned u) {
    return (u & 0x80000000u) ? __uint_as_float(u ^ 0x80000000u) : __uint_as_float(~u);
}
__device__ __forceinline__ int warp_incl_scan(int v, int lane) {
    #pragma unroll
    for (int o = 1; o < 32; o <<= 1) {
        int n = __shfl_up_sync(0xffffffffu, v, o);
        if (lane >= o) v += n;
    }
    return v;
}

__global__ __launch_bounds__(128) void topk_attn_kernel(
    const float* __restrict__ logits, const float* __restrict__ vp,
    float* __restrict__ mix, float* __restrict__ attn, int write_attn)
{
    const int row = blockIdx.x;          // bh*LQ + q
    const int bh  = row >> 11;
    const int qi  = row & 2047;
    const int b   = bh >> 4;
    const int h   = bh & 15;
    const int tid = threadIdx.x;
    const int lane = tid & 31;
    const int wid  = tid >> 5;

    __shared__ unsigned su[LK_];
    __shared__ int      hist[256];
    __shared__ int      wtot[4];
    __shared__ float    wsum[4];
    __shared__ unsigned wmax[4];
    __shared__ int      sel_idx[TOPK_];
    __shared__ float    sel_w[TOPK_];
    __shared__ unsigned s_prefix;
    __shared__ int      s_k;
    __shared__ float    s_max, s_invZ;

    // --- Load row (float4), encode keys, local max; zero-fill attn row ---
    const float4* lrow4 = (const float4*)(logits + (size_t)row * LK_);
    float4* arow4 = (float4*)(attn + (size_t)row * LK_);
    unsigned lm = 0u;
    #pragma unroll
    for (int it = 0; it < 4; it++) {
        int i4 = tid + it * 128;
        float4 x = lrow4[i4];
        unsigned e0 = encf(x.x), e1 = encf(x.y), e2 = encf(x.z), e3 = encf(x.w);
        su[4*i4+0] = e0; su[4*i4+1] = e1; su[4*i4+2] = e2; su[4*i4+3] = e3;
        unsigned m01 = e0 > e1 ? e0 : e1;
        unsigned m23 = e2 > e3 ? e2 : e3;
        unsigned m = m01 > m23 ? m01 : m23;
        lm = lm > m ? lm : m;
        if (write_attn) arow4[i4] = make_float4(0.f, 0.f, 0.f, 0.f);
    }
    #pragma unroll
    for (int o = 16; o > 0; o >>= 1) {
        unsigned v = __shfl_xor_sync(0xffffffffu, lm, o);
        lm = lm > v ? lm : v;
    }
    if (lane == 0) wmax[wid] = lm;
    if (tid == 0) { s_prefix = 0u; s_k = TOPK_; }
    __syncthreads();
    if (tid == 0) {
        unsigned m = wmax[0];
        m = m > wmax[1] ? m : wmax[1];
        m = m > wmax[2] ? m : wmax[2];
        m = m > wmax[3] ? m : wmax[3];
        s_max = decf(m);
    }
    __syncthreads();
    const float rowmax = s_max;

    // --- Radix select (MSB-first, 8-bit digits, parallel digit selection) ---
    unsigned pmask = 0u;
    for (int shift = 24; shift >= 0; shift -= 8) {
        hist[tid] = 0; hist[tid + 128] = 0;
        __syncthreads();
        const unsigned pref = s_prefix;
        const int kk = s_k;
        #pragma unroll 4
        for (int it = 0; it < 16; it++) {
            unsigned u = su[tid + it * 128];
            bool valid = ((u & pmask) == pref);
            int d = (int)((u >> shift) & 255u);
            int key = valid ? d : (256 + lane);
            unsigned mm = __match_any_sync(0xffffffffu, key);
            if (valid && ((int)(__ffs(mm) - 1) == lane))
                atomicAdd(&hist[d], __popc(mm));
        }
        __syncthreads();
        // suffix sums over 256 bins: thread t owns bins {2t, 2t+1}
        int h0 = hist[2*tid], h1 = hist[2*tid+1];
        int ps = h0 + h1;
        int incl = warp_incl_scan(ps, lane);
        if (lane == 31) wtot[wid] = incl;
        __syncthreads();
        int base = 0;
        #pragma unroll
        for (int w2 = 0; w2 < 4; w2++) if (w2 < wid) base += wtot[w2];
        int Tot = wtot[0] + wtot[1] + wtot[2] + wtot[3];
        int inclAll = incl + base;
        int S0 = Tot - inclAll + ps;   // S(2t)   = sum hist[2t..255]
        int S1 = S0 - h0;              // S(2t+1)
        int S2 = S0 - ps;              // S(2t+2)
        if (S0 >= kk && S1 < kk) { s_prefix = pref | ((unsigned)(2*tid)   << shift); s_k = kk - S1; }
        if (S1 >= kk && S2 < kk) { s_prefix = pref | ((unsigned)(2*tid+1) << shift); s_k = kk - S2; }
        __syncthreads();
        pmask |= (0xffu << shift);
    }
    const unsigned uT = s_prefix;
    const int kfin = s_k;            // # of ==uT to keep (lowest index first)
    const int Gtot = TOPK_ - kfin;   // # strictly greater

    // --- Parallel marking + compaction: blocked ownership [16t, 16t+16) ---
    const int base16 = tid * 16;
    int g = 0, e = 0;
    #pragma unroll
    for (int j = 0; j < 16; j++) {
        unsigned u = su[base16 + j];
        g += (u > uT);
        e += (u == uT);
    }
    int packed = (g << 16) | e;
    int incl = warp_incl_scan(packed, lane);
    if (lane == 31) wtot[wid] = incl;
    __syncthreads();
    int basep = 0;
    #pragma unroll
    for (int w2 = 0; w2 < 4; w2++) if (w2 < wid) basep += wtot[w2];
    int excl = incl - packed + basep;
    int gp = excl >> 16;
    int ep = excl & 0xffff;

    float zl = 0.f;
    #pragma unroll
    for (int j = 0; j < 16; j++) {
        int i = base16 + j;
        unsigned u = su[i];
        if (u > uT) {
            float w = expf(decf(u) - rowmax);
            sel_idx[gp] = i; sel_w[gp] = w; zl += w; gp++;
        } else if (u == uT) {
            if (ep < kfin) {
                float w = expf(decf(u) - rowmax);
                sel_idx[Gtot + ep] = i; sel_w[Gtot + ep] = w; zl += w;
            }
            ep++;
        }
    }
    #pragma unroll
    for (int o = 16; o > 0; o >>= 1) zl += __shfl_xor_sync(0xffffffffu, zl, o);
    if (lane == 0) wsum[wid] = zl;
    __syncthreads();
    if (tid == 0) s_invZ = 1.0f / (wsum[0] + wsum[1] + wsum[2] + wsum[3]);
    __syncthreads();
    const float invZ = s_invZ;
    if (tid < TOPK_) sel_w[tid] *= invZ;
    __syncthreads();

    // --- Scatter attn weights (row already zero-filled) ---
    if (write_attn && tid < TOPK_)
        attn[(size_t)row * LK_ + sel_idx[tid]] = sel_w[tid];

    // --- Sparse AV: mix[b,q,h,d] = sum_s w_s * vp[bh, idx_s, d] ---
    {
        const int d = tid & 63, half = tid >> 6;
        const float* vb = vp + (size_t)bh * LK_ * 64;
        float accv = 0.f;
        for (int s = half; s < TOPK_; s += 2)
            accv += sel_w[s] * vb[(size_t)sel_idx[s] * 64 + d];
        // combine the two halves via shared
        __shared__ float sred[128];
        sred[tid] = accv;
        __syncthreads();
        if (tid < 64)
            mix[((size_t)(b * LQ_ + qi)) * (HH * DVV) + h * 64 + tid] =
                sred[tid] + sred[tid + 64];
    }
}

// ---------------------------------------------------------------------------
extern "C" void kernel_launch(void* const* d_in, const int* in_sizes, int n_in,
                              void* d_out, int out_size) {
    (void)in_sizes; (void)n_in;
    const float* q    = (const float*)d_in[0];
    const float* k    = (const float*)d_in[1];
    const float* v    = (const float*)d_in[2];
    const float* w_qs = (const float*)d_in[3];
    const float* w_ks = (const float*)d_in[4];
    const float* w_vs = (const float*)d_in[5];
    const float* fc   = (const float*)d_in[6];
    float* out = (float*)d_out;

    float *qp, *kp, *vp, *mix, *lg;
    cudaGetSymbolAddress((void**)&qp,  g_qp);
    cudaGetSymbolAddress((void**)&kp,  g_kp);
    cudaGetSymbolAddress((void**)&vp,  g_vp);
    cudaGetSymbolAddress((void**)&mix, g_mix);
    cudaGetSymbolAddress((void**)&lg,  g_logits);

    dim3 blk(256);
    // QP = (q @ w_qs^T) * 0.125   [M=4096, N=1024, K=1024]
    sgemm128<<<dim3(8, 32, 1), blk>>>(q, w_qs, qp, BB*LQ_, HH*DKK, EE, 0, 0.125f, LQ_, 0, 0, 0);
    // KP = k @ w_ks^T
    sgemm128<<<dim3(8, 32, 1), blk>>>(k, w_ks, kp, BB*LK_, HH*DKK, EE, 0, 1.0f, LK_, 0, 0, 0);
    // VP = v @ w_vs^T             [M=4096, N=1024, K=64]
    sgemm128<<<dim3(8, 32, 1), blk>>>(v, w_vs, vp, BB*LK_, HH*DVV, DVV, 0, 1.0f, LK_, 0, 0, 0);
    // logits[bh] = QP[bh] @ KP[bh]^T   [2048 x 2048 x 64] x 32 planes
    sgemm128<<<dim3(16, 16, BB*HH), blk>>>(qp, kp, lg, LQ_, LK_, DKK, 1, 1.0f, 0,
                                           (size_t)LQ_ * DKK, (size_t)LK_ * DKK,
                                           (size_t)LQ_ * LK_);

    const long long out_elems  = (long long)BB * LQ_ * DVV;           // 262144
    const long long attn_elems = (long long)BB * HH * LQ_ * LK_;      // 134217728
    int write_attn = ((long long)out_size >= out_elems + attn_elems) ? 1 : 0;

    topk_attn_kernel<<<BB * HH * LQ_, 128>>>(lg, vp, mix, out + out_elems, write_attn);

    // out = mix @ fc^T  [M=4096, N=64, K=1024]
    sgemm_nt<<<dim3(1, 64, 1), blk>>>(mix, fc, out, BB*LQ_, DVV, HH*DVV, 1.0f);
}

// round 3
// speedup vs baseline: 2.5364x; 2.3899x over previous
#include <cuda_runtime.h>
#include <cuda_bf16.h>
#include <math.h>

// Problem constants
#define BB    2
#define LQ_   2048
#define LK_   2048
#define EE    1024
#define HH    16
#define DKK   64
#define DVV   64
#define TOPK_ 64

// Device scratch (allocation-free rule: static __device__ arrays)
__device__ __align__(256) float g_qp[BB*HH*LQ_*DKK];
__device__ __align__(256) float g_kp[BB*HH*LK_*DKK];
__device__ __align__(256) float g_vp[BB*HH*LK_*DVV];
__device__ __align__(256) float g_mix[BB*LQ_*HH*DVV];
__device__ __align__(256) float g_logits[(size_t)BB*HH*LQ_*LK_]; // 512MB

// --------------------------- f32x2 helpers --------------------------------
typedef unsigned long long ull;
__device__ __forceinline__ ull dup2(float x) {
    ull r; asm("mov.b64 %0, {%1, %1};" : "=l"(r) : "f"(x)); return r;
}
__device__ __forceinline__ ull fma2(ull a, ull b, ull c) {
    ull d; asm("fma.rn.f32x2 %0, %1, %2, %3;" : "=l"(d) : "l"(a), "l"(b), "l"(c)); return d;
}
__device__ __forceinline__ float2 unp2(ull p) {
    float2 f; asm("mov.b64 {%0, %1}, %2;" : "=f"(f.x), "=f"(f.y) : "l"(p)); return f;
}

// ---------------------------------------------------------------------------
// 128x128 tile, 8x8 micro-tile SGEMM with packed f32x2 FMA.
// C = A * W^T.  A:[M,K], W:[N,K] row-major.  K%16==0, M%128==0, N%128==0.
// mode 0: scatter n=(h*64+d), m=(b*Lrows+l) -> [(b*nH+h)*Lrows+l]*64+d
// mode 1: row-major [M,N].  Batched via blockIdx.z.
// ---------------------------------------------------------------------------
__global__ void __launch_bounds__(256, 2) sgemm128(
    const float* __restrict__ A, const float* __restrict__ W, float* __restrict__ C,
    int M, int N, int K, int mode, float scale, int Lrows,
    size_t sA, size_t sW, size_t sC)
{
    A += (size_t)blockIdx.z * sA;
    W += (size_t)blockIdx.z * sW;
    C += (size_t)blockIdx.z * sC;
    const int m0 = blockIdx.y * 128;
    const int n0 = blockIdx.x * 128;
    const int tid = threadIdx.x;
    const int ty = tid >> 4;
    const int tx = tid & 15;

    __shared__ __align__(16) float As[16][132];
    __shared__ __align__(16) float Ws[16][132];

    ull accp[8][4];
    #pragma unroll
    for (int i = 0; i < 8; i++)
        #pragma unroll
        for (int j = 0; j < 4; j++) accp[i][j] = 0ull;

    for (int kt = 0; kt < K; kt += 16) {
        #pragma unroll
        for (int i = 0; i < 2; i++) {
            int f  = tid + i * 256;
            int r  = f >> 2;
            int c4 = (f & 3) << 2;
            float4 a = *(const float4*)(A + (size_t)(m0 + r) * K + kt + c4);
            As[c4+0][r] = a.x; As[c4+1][r] = a.y; As[c4+2][r] = a.z; As[c4+3][r] = a.w;
            float4 w = *(const float4*)(W + (size_t)(n0 + r) * K + kt + c4);
            Ws[c4+0][r] = w.x; Ws[c4+1][r] = w.y; Ws[c4+2][r] = w.z; Ws[c4+3][r] = w.w;
        }
        __syncthreads();
        #pragma unroll
        for (int e = 0; e < 16; e++) {
            float4 a0 = *(const float4*)&As[e][ty * 8];
            float4 a1 = *(const float4*)&As[e][ty * 8 + 4];
            ulonglong2 bp0 = *(const ulonglong2*)&Ws[e][tx * 8];
            ulonglong2 bp1 = *(const ulonglong2*)&Ws[e][tx * 8 + 4];
            ull bv[4] = {bp0.x, bp0.y, bp1.x, bp1.y};
            float av[8] = {a0.x, a0.y, a0.z, a0.w, a1.x, a1.y, a1.z, a1.w};
            #pragma unroll
            for (int i = 0; i < 8; i++) {
                ull ad = dup2(av[i]);
                #pragma unroll
                for (int j = 0; j < 4; j++)
                    accp[i][j] = fma2(ad, bv[j], accp[i][j]);
            }
        }
        __syncthreads();
    }

    const int nH = N >> 6;
    #pragma unroll
    for (int i = 0; i < 8; i++) {
        int m = m0 + ty * 8 + i;
        #pragma unroll
        for (int j2 = 0; j2 < 2; j2++) {
            float2 p0 = unp2(accp[i][j2*2+0]);
            float2 p1 = unp2(accp[i][j2*2+1]);
            float4 o = make_float4(p0.x*scale, p0.y*scale, p1.x*scale, p1.y*scale);
            int n = n0 + tx * 8 + j2 * 4;
            if (mode == 0) {
                int b = m / Lrows, l = m - b * Lrows;
                int h = n >> 6, d = n & 63;
                *(float4*)&C[(((size_t)b * nH + h) * Lrows + l) * 64 + d] = o;
            } else {
                *(float4*)&C[(size_t)m * N + n] = o;
            }
        }
    }
}

// ---------------------------------------------------------------------------
// Small GEMM kept for fc (N=64): C = A*W^T, 64x64 tile, 4x4 micro.
// ---------------------------------------------------------------------------
__global__ __launch_bounds__(256) void sgemm_nt(
    const float* __restrict__ A, const float* __restrict__ W, float* __restrict__ C,
    int M, int N, int K, float scale)
{
    const int m0 = blockIdx.y * 64;
    const int n0 = blockIdx.x * 64;
    const int tid = threadIdx.x;
    const int ty = tid >> 4;
    const int tx = tid & 15;

    __shared__ __align__(16) float As[32][68];
    __shared__ __align__(16) float Ws[32][68];

    float acc[4][4];
    #pragma unroll
    for (int i = 0; i < 4; i++)
        #pragma unroll
        for (int j = 0; j < 4; j++) acc[i][j] = 0.f;

    for (int kt = 0; kt < K; kt += 32) {
        #pragma unroll
        for (int i = 0; i < 2; i++) {
            int f  = tid + i * 256;
            int r  = f >> 3;
            int c4 = (f & 7) << 2;
            float4 a = *(const float4*)(A + (size_t)(m0 + r) * K + kt + c4);
            As[c4+0][r] = a.x; As[c4+1][r] = a.y; As[c4+2][r] = a.z; As[c4+3][r] = a.w;
            float4 w = *(const float4*)(W + (size_t)(n0 + r) * K + kt + c4);
            Ws[c4+0][r] = w.x; Ws[c4+1][r] = w.y; Ws[c4+2][r] = w.z; Ws[c4+3][r] = w.w;
        }
        __syncthreads();
        #pragma unroll
        for (int e = 0; e < 32; e++) {
            float4 ra = *(const float4*)&As[e][ty << 2];
            float4 rb = *(const float4*)&Ws[e][tx << 2];
            float av[4] = {ra.x, ra.y, ra.z, ra.w};
            float bv[4] = {rb.x, rb.y, rb.z, rb.w};
            #pragma unroll
            for (int i = 0; i < 4; i++)
                #pragma unroll
                for (int j = 0; j < 4; j++)
                    acc[i][j] += av[i] * bv[j];
        }
        __syncthreads();
    }
    #pragma unroll
    for (int i = 0; i < 4; i++) {
        int m = m0 + (ty << 2) + i;
        #pragma unroll
        for (int j = 0; j < 4; j++) {
            int n = n0 + (tx << 2) + j;
            C[(size_t)m * N + n] = acc[i][j] * scale;
        }
    }
}

// ---------------------------------------------------------------------------
// Streaming zero-fill (attn region)
// ---------------------------------------------------------------------------
__global__ __launch_bounds__(256) void zerofill(float4* __restrict__ p, size_t n4) {
    size_t i = (size_t)blockIdx.x * blockDim.x + threadIdx.x;
    size_t stride = (size_t)gridDim.x * blockDim.x;
    float4 z = make_float4(0.f, 0.f, 0.f, 0.f);
    for (; i < n4; i += stride) p[i] = z;
}

// ---------------------------------------------------------------------------
// Top-k + softmax + sparse AV (candidate-narrowing radix select)
// ---------------------------------------------------------------------------
__device__ __forceinline__ unsigned encf(float x) {
    unsigned u = __float_as_uint(x);
    return (u & 0x80000000u) ? ~u : (u | 0x80000000u);
}
__device__ __forceinline__ float decf(unsigned u) {
    return (u & 0x80000000u) ? __uint_as_float(u ^ 0x80000000u) : __uint_as_float(~u);
}
__device__ __forceinline__ int warp_incl_scan(int v, int lane) {
    #pragma unroll
    for (int o = 1; o < 32; o <<= 1) {
        int n = __shfl_up_sync(0xffffffffu, v, o);
        if (lane >= o) v += n;
    }
    return v;
}
// all-lane-uniform ballot compaction; returns position (valid only if flag)
__device__ __forceinline__ int ballot_append(bool flag, int* counter, int lane) {
    unsigned m = __ballot_sync(0xffffffffu, flag);
    int base = 0;
    if (m) {
        int leader = __ffs(m) - 1;
        if (lane == leader) base = atomicAdd(counter, __popc(m));
        base = __shfl_sync(0xffffffffu, base, leader);
    }
    return base + __popc(m & ((1u << lane) - 1u));
}

// Picks digit d s.t. suffix-count crosses kk; writes *s_d=d, *s_k = kk - S(d+1).
__device__ __forceinline__ void pick_digit(int* hist, int kk, int tid, int lane,
                                           int wid, int* wtot, int* s_d, int* s_k) {
    int h0 = hist[2*tid], h1 = hist[2*tid+1];
    int ps = h0 + h1;
    int incl = warp_incl_scan(ps, lane);
    if (lane == 31) wtot[wid] = incl;
    __syncthreads();
    int base = 0;
    #pragma unroll
    for (int w2 = 0; w2 < 4; w2++) if (w2 < wid) base += wtot[w2];
    int Tot = wtot[0] + wtot[1] + wtot[2] + wtot[3];
    int inclAll = incl + base;
    int S0 = Tot - inclAll + ps;     // sum hist[2t..255]
    int S1 = S0 - h0;
    int S2 = S0 - ps;
    if (S0 >= kk && S1 < kk) { *s_d = 2*tid;   *s_k = kk - S1; }
    if (S1 >= kk && S2 < kk) { *s_d = 2*tid+1; *s_k = kk - S2; }
    __syncthreads();
}

__global__ __launch_bounds__(128) void topk_attn_kernel(
    const float* __restrict__ logits, const float* __restrict__ vp,
    float* __restrict__ mix, float* __restrict__ attn, int write_attn)
{
    const int row = blockIdx.x;          // bh*LQ + q
    const int bh  = row >> 11;
    const int qi  = row & 2047;
    const int b   = bh >> 4;
    const int h   = bh & 15;
    const int tid = threadIdx.x;
    const int lane = tid & 31;
    const int wid  = tid >> 5;

    __shared__ unsigned su[LK_];         // 8KB
    __shared__ int      cand[LK_];       // 8KB (worst case)
    __shared__ int      hist[256];
    __shared__ int      wtot[4];
    __shared__ unsigned wmax[4];
    __shared__ float    wsum[2];
    __shared__ int      sel_idx[TOPK_];
    __shared__ float    sel_w[TOPK_];
    __shared__ float    sred[128];
    __shared__ int      s_d, s_k, s_nsel, s_ncand;
    __shared__ float    s_max, s_invZ;

    // --- Load row (float4), encode keys, rowmax ---
    const float4* lrow4 = (const float4*)(logits + (size_t)row * LK_);
    unsigned lm = 0u;
    #pragma unroll
    for (int it = 0; it < 4; it++) {
        int i4 = tid + it * 128;
        float4 x = lrow4[i4];
        unsigned e0 = encf(x.x), e1 = encf(x.y), e2 = encf(x.z), e3 = encf(x.w);
        su[4*i4+0] = e0; su[4*i4+1] = e1; su[4*i4+2] = e2; su[4*i4+3] = e3;
        unsigned m01 = e0 > e1 ? e0 : e1;
        unsigned m23 = e2 > e3 ? e2 : e3;
        unsigned m = m01 > m23 ? m01 : m23;
        lm = lm > m ? lm : m;
    }
    #pragma unroll
    for (int o = 16; o > 0; o >>= 1) {
        unsigned v = __shfl_xor_sync(0xffffffffu, lm, o);
        lm = lm > v ? lm : v;
    }
    if (lane == 0) wmax[wid] = lm;
    if (tid == 0) { s_nsel = 0; s_ncand = 0; }
    hist[tid] = 0; hist[tid + 128] = 0;
    __syncthreads();
    if (tid == 0) {
        unsigned m = wmax[0];
        m = m > wmax[1] ? m : wmax[1];
        m = m > wmax[2] ? m : wmax[2];
        m = m > wmax[3] ? m : wmax[3];
        s_max = decf(m);
    }

    // --- Pass 1: 8-bit histogram of top byte over all 2048 ---
    #pragma unroll 4
    for (int it = 0; it < 16; it++) {
        unsigned u = su[tid + it * 128];
        int d = (int)(u >> 24);
        unsigned mm = __match_any_sync(0xffffffffu, d);
        if ((int)(__ffs(mm) - 1) == lane) atomicAdd(&hist[d], __popc(mm));
    }
    __syncthreads();
    pick_digit(hist, TOPK_, tid, lane, wid, wtot, &s_d, &s_k);
    const float rowmax = s_max;
    int d1 = s_d;
    int kk = s_k;

    // --- Compact: top byte > d1 -> selected; == d1 -> candidates ---
    #pragma unroll
    for (int it = 0; it < 16; it++) {
        int i = tid + it * 128;
        unsigned dg = su[i] >> 24;
        bool is_g = (int)dg > d1;
        bool is_e = (int)dg == d1;
        int pg = ballot_append(is_g, &s_nsel, lane);
        if (is_g) sel_idx[pg] = i;
        int pe = ballot_append(is_e, &s_ncand, lane);
        if (is_e) cand[pe] = i;
    }
    __syncthreads();
    int C = s_ncand;

    // --- Passes 2..4 over shrinking candidate list ---
    for (int shift = 16; shift >= 0; shift -= 8) {
        if (C == kk) break;
        hist[tid] = 0; hist[tid + 128] = 0;
        __syncthreads();
        for (int c0 = 0; c0 < C; c0 += 128) {
            int c = c0 + tid;
            if (c < C) atomicAdd(&hist[(su[cand[c]] >> shift) & 255u], 1);
        }
        __syncthreads();
        pick_digit(hist, kk, tid, lane, wid, wtot, &s_d, &s_k);
        int d = s_d;
        // buffer my entries before rewriting cand
        int mine[16]; int nm = 0;
        for (int c0 = 0; c0 < C; c0 += 128) {
            int c = c0 + tid;
            if (c < C) mine[nm++] = cand[c];
        }
        __syncthreads();
        if (tid == 0) s_ncand = 0;
        __syncthreads();
        int Cpad = (C + 127) & ~127;
        int used = 0;
        for (int c0 = 0; c0 < Cpad; c0 += 128) {
            int c = c0 + tid;
            bool active = (c < C);
            int idx = active ? mine[used] : 0;
            if (active) used++;
            unsigned dg = active ? ((su[idx] >> shift) & 255u) : 0u;
            bool is_g = active && ((int)dg > d);
            bool is_e = active && ((int)dg == d);
            int pg = ballot_append(is_g, &s_nsel, lane);
            if (is_g) sel_idx[pg] = idx;
            int pe = ballot_append(is_e, &s_ncand, lane);
            if (is_e) cand[pe] = idx;
        }
        __syncthreads();
        C = s_ncand;
        kk = s_k;
    }

    // --- Finish: remaining candidates all share the needed key prefix ---
    if (C == kk) {
        for (int c0 = 0; c0 < C; c0 += 128) {
            int c = c0 + tid;
            if (c < C) { int pos = atomicAdd(&s_nsel, 1); sel_idx[pos] = cand[c]; }
        }
    } else {
        // full keys equal: take kk lowest indices (jax top_k tie semantics)
        for (int c0 = 0; c0 < C; c0 += 128) {
            int c = c0 + tid;
            if (c < C) {
                int idx = cand[c];
                int r = 0;
                for (int j = 0; j < C; j++) r += (cand[j] < idx);
                if (r < kk) { int pos = atomicAdd(&s_nsel, 1); sel_idx[pos] = idx; }
            }
        }
    }
    __syncthreads();

    // --- Softmax over the 64 selected ---
    float w = 0.f;
    if (tid < TOPK_) {
        w = expf(decf(su[sel_idx[tid]]) - rowmax);
        sel_w[tid] = w;
    }
    float zl = w;
    #pragma unroll
    for (int o = 16; o > 0; o >>= 1) zl += __shfl_xor_sync(0xffffffffu, zl, o);
    if (tid < TOPK_ && lane == 0) wsum[wid] = zl;
    __syncthreads();
    if (tid == 0) s_invZ = 1.0f / (wsum[0] + wsum[1]);
    __syncthreads();
    const float invZ = s_invZ;
    if (tid < TOPK_) sel_w[tid] = sel_w[tid] * invZ;
    __syncthreads();

    // --- Scatter attn weights (row pre-zeroed by zerofill kernel) ---
    if (write_attn && tid < TOPK_)
        attn[(size_t)row * LK_ + sel_idx[tid]] = sel_w[tid];

    // --- Sparse AV: mix[b,q,h,d] = sum_s w_s * vp[bh, idx_s, d] ---
    {
        const int d = tid & 63, half = tid >> 6;
        const float* vb = vp + (size_t)bh * LK_ * 64;
        float accv = 0.f;
        for (int s = half; s < TOPK_; s += 2)
            accv += sel_w[s] * vb[(size_t)sel_idx[s] * 64 + d];
        sred[tid] = accv;
        __syncthreads();
        if (tid < 64)
            mix[((size_t)(b * LQ_ + qi)) * (HH * DVV) + h * 64 + tid] =
                sred[tid] + sred[tid + 64];
    }
}

// ---------------------------------------------------------------------------
extern "C" void kernel_launch(void* const* d_in, const int* in_sizes, int n_in,
                              void* d_out, int out_size) {
    (void)in_sizes; (void)n_in;
    const float* q    = (const float*)d_in[0];
    const float* k    = (const float*)d_in[1];
    const float* v    = (const float*)d_in[2];
    const float* w_qs = (const float*)d_in[3];
    const float* w_ks = (const float*)d_in[4];
    const float* w_vs = (const float*)d_in[5];
    const float* fc   = (const float*)d_in[6];
    float* out = (float*)d_out;

    float *qp, *kp, *vp, *mix, *lg;
    cudaGetSymbolAddress((void**)&qp,  g_qp);
    cudaGetSymbolAddress((void**)&kp,  g_kp);
    cudaGetSymbolAddress((void**)&vp,  g_vp);
    cudaGetSymbolAddress((void**)&mix, g_mix);
    cudaGetSymbolAddress((void**)&lg,  g_logits);

    const long long out_elems  = (long long)BB * LQ_ * DVV;           // 262144
    const long long attn_elems = (long long)BB * HH * LQ_ * LK_;      // 134217728
    int write_attn = ((long long)out_size >= out_elems + attn_elems) ? 1 : 0;
    float* attn = out + out_elems;

    dim3 blk(256);
    // QP = (q @ w_qs^T) * 0.125
    sgemm128<<<dim3(8, 32, 1), blk>>>(q, w_qs, qp, BB*LQ_, HH*DKK, EE, 0, 0.125f, LQ_, 0, 0, 0);
    // KP = k @ w_ks^T
    sgemm128<<<dim3(8, 32, 1), blk>>>(k, w_ks, kp, BB*LK_, HH*DKK, EE, 0, 1.0f, LK_, 0, 0, 0);
    // VP = v @ w_vs^T
    sgemm128<<<dim3(8, 32, 1), blk>>>(v, w_vs, vp, BB*LK_, HH*DVV, DVV, 0, 1.0f, LK_, 0, 0, 0);
    // logits[bh] = QP[bh] @ KP[bh]^T
    sgemm128<<<dim3(16, 16, BB*HH), blk>>>(qp, kp, lg, LQ_, LK_, DKK, 1, 1.0f, 0,
                                           (size_t)LQ_ * DKK, (size_t)LK_ * DKK,
                                           (size_t)LQ_ * LK_);
    // zero attn region (streaming)
    if (write_attn)
        zerofill<<<16384, 256>>>((float4*)attn, (size_t)attn_elems / 4);

    topk_attn_kernel<<<BB * HH * LQ_, 128>>>(lg, vp, mix, attn, write_attn);

    // out = mix @ fc^T
    sgemm_nt<<<dim3(1, 64, 1), blk>>>(mix, fc, out, BB*LQ_, DVV, HH*DVV, 1.0f);
}

// round 4
// speedup vs baseline: 2.5803x; 1.0173x over previous
#include <cuda_runtime.h>
#include <cuda_bf16.h>
#include <math.h>

// Problem constants
#define BB    2
#define LQ_   2048
#define LK_   2048
#define EE    1024
#define HH    16
#define DKK   64
#define DVV   64
#define TOPK_ 64

// Device scratch
__device__ __align__(256) float g_qp[BB*HH*LQ_*DKK];
__device__ __align__(256) float g_kp[BB*HH*LK_*DKK];
__device__ __align__(256) float g_vp[BB*HH*LK_*DVV];
__device__ __align__(256) float g_mix[BB*LQ_*HH*DVV];
__device__ __align__(256) float g_logits[(size_t)BB*HH*LQ_*LK_]; // 512MB

// --------------------------- f32x2 helpers --------------------------------
typedef unsigned long long ull;
__device__ __forceinline__ ull dup2(float x) {
    ull r; asm("mov.b64 %0, {%1, %1};" : "=l"(r) : "f"(x)); return r;
}
__device__ __forceinline__ ull fma2(ull a, ull b, ull c) {
    ull d; asm("fma.rn.f32x2 %0, %1, %2, %3;" : "=l"(d) : "l"(a), "l"(b), "l"(c)); return d;
}
__device__ __forceinline__ float2 unp2(ull p) {
    float2 f; asm("mov.b64 {%0, %1}, %2;" : "=f"(f.x), "=f"(f.y) : "l"(p)); return f;
}

// ---------------------------------------------------------------------------
// 128x128 tile, 8x8 micro-tile SGEMM, f32x2 FMA, double-buffered smem (K-tile 8).
// C = A * W^T.  A:[M,K], W:[N,K] row-major.  K%8==0, M%128==0, N%128==0.
// mode 0: scatter n=(h*64+d), m=(b*Lrows+l) -> [(b*nH+h)*Lrows+l]*64+d
// mode 1: row-major [M,N].  Batched via blockIdx.z.
// ---------------------------------------------------------------------------
__global__ void __launch_bounds__(256, 2) sgemm128(
    const float* __restrict__ A, const float* __restrict__ W, float* __restrict__ C,
    int M, int N, int K, int mode, float scale, int Lrows,
    size_t sA, size_t sW, size_t sC)
{
    A += (size_t)blockIdx.z * sA;
    W += (size_t)blockIdx.z * sW;
    C += (size_t)blockIdx.z * sC;
    const int m0 = blockIdx.y * 128;
    const int n0 = blockIdx.x * 128;
    const int tid = threadIdx.x;
    const int ty = tid >> 4;
    const int tx = tid & 15;

    // loader mapping: 256 threads cover 128 rows x 8 k as 256 float4
    const int lr = tid >> 1;          // row 0..127
    const int lc = (tid & 1) << 2;    // k offset 0 or 4

    __shared__ __align__(16) float As[2][8][132];
    __shared__ __align__(16) float Ws[2][8][132];

    ull accp[8][4];
    #pragma unroll
    for (int i = 0; i < 8; i++)
        #pragma unroll
        for (int j = 0; j < 4; j++) accp[i][j] = 0ull;

    const float* Arow = A + (size_t)(m0 + lr) * K + lc;
    const float* Wrow = W + (size_t)(n0 + lr) * K + lc;

    // prologue: tile 0 -> buf 0
    {
        float4 a = *(const float4*)(Arow);
        float4 w = *(const float4*)(Wrow);
        As[0][lc+0][lr] = a.x; As[0][lc+1][lr] = a.y; As[0][lc+2][lr] = a.z; As[0][lc+3][lr] = a.w;
        Ws[0][lc+0][lr] = w.x; Ws[0][lc+1][lr] = w.y; Ws[0][lc+2][lr] = w.z; Ws[0][lc+3][lr] = w.w;
    }
    __syncthreads();

    const int nT = K >> 3;
    for (int t = 0; t < nT; t++) {
        const int cur = t & 1;
        float4 an, wn;
        const bool more = (t + 1 < nT);
        if (more) {
            an = *(const float4*)(Arow + (t + 1) * 8);
            wn = *(const float4*)(Wrow + (t + 1) * 8);
        }
        #pragma unroll
        for (int e = 0; e < 8; e++) {
            float4 a0 = *(const float4*)&As[cur][e][ty * 8];
            float4 a1 = *(const float4*)&As[cur][e][ty * 8 + 4];
            ulonglong2 bp0 = *(const ulonglong2*)&Ws[cur][e][tx * 8];
            ulonglong2 bp1 = *(const ulonglong2*)&Ws[cur][e][tx * 8 + 4];
            ull bv[4] = {bp0.x, bp0.y, bp1.x, bp1.y};
            float av[8] = {a0.x, a0.y, a0.z, a0.w, a1.x, a1.y, a1.z, a1.w};
            #pragma unroll
            for (int i = 0; i < 8; i++) {
                ull ad = dup2(av[i]);
                #pragma unroll
                for (int j = 0; j < 4; j++)
                    accp[i][j] = fma2(ad, bv[j], accp[i][j]);
            }
        }
        if (more) {
            const int nxt = cur ^ 1;
            As[nxt][lc+0][lr] = an.x; As[nxt][lc+1][lr] = an.y;
            As[nxt][lc+2][lr] = an.z; As[nxt][lc+3][lr] = an.w;
            Ws[nxt][lc+0][lr] = wn.x; Ws[nxt][lc+1][lr] = wn.y;
            Ws[nxt][lc+2][lr] = wn.z; Ws[nxt][lc+3][lr] = wn.w;
            __syncthreads();
        }
    }

    const int nH = N >> 6;
    #pragma unroll
    for (int i = 0; i < 8; i++) {
        int m = m0 + ty * 8 + i;
        #pragma unroll
        for (int j2 = 0; j2 < 2; j2++) {
            float2 p0 = unp2(accp[i][j2*2+0]);
            float2 p1 = unp2(accp[i][j2*2+1]);
            float4 o = make_float4(p0.x*scale, p0.y*scale, p1.x*scale, p1.y*scale);
            int n = n0 + tx * 8 + j2 * 4;
            if (mode == 0) {
                int b = m / Lrows, l = m - b * Lrows;
                int h = n >> 6, d = n & 63;
                *(float4*)&C[(((size_t)b * nH + h) * Lrows + l) * 64 + d] = o;
            } else {
                *(float4*)&C[(size_t)m * N + n] = o;
            }
        }
    }
}

// ---------------------------------------------------------------------------
// Small GEMM kept for fc (N=64): C = A*W^T, 64x64 tile, 4x4 micro.
// ---------------------------------------------------------------------------
__global__ __launch_bounds__(256) void sgemm_nt(
    const float* __restrict__ A, const float* __restrict__ W, float* __restrict__ C,
    int M, int N, int K, float scale)
{
    const int m0 = blockIdx.y * 64;
    const int n0 = blockIdx.x * 64;
    const int tid = threadIdx.x;
    const int ty = tid >> 4;
    const int tx = tid & 15;

    __shared__ __align__(16) float As[32][68];
    __shared__ __align__(16) float Ws[32][68];

    float acc[4][4];
    #pragma unroll
    for (int i = 0; i < 4; i++)
        #pragma unroll
        for (int j = 0; j < 4; j++) acc[i][j] = 0.f;

    for (int kt = 0; kt < K; kt += 32) {
        #pragma unroll
        for (int i = 0; i < 2; i++) {
            int f  = tid + i * 256;
            int r  = f >> 3;
            int c4 = (f & 7) << 2;
            float4 a = *(const float4*)(A + (size_t)(m0 + r) * K + kt + c4);
            As[c4+0][r] = a.x; As[c4+1][r] = a.y; As[c4+2][r] = a.z; As[c4+3][r] = a.w;
            float4 w = *(const float4*)(W + (size_t)(n0 + r) * K + kt + c4);
            Ws[c4+0][r] = w.x; Ws[c4+1][r] = w.y; Ws[c4+2][r] = w.z; Ws[c4+3][r] = w.w;
        }
        __syncthreads();
        #pragma unroll
        for (int e = 0; e < 32; e++) {
            float4 ra = *(const float4*)&As[e][ty << 2];
            float4 rb = *(const float4*)&Ws[e][tx << 2];
            float av[4] = {ra.x, ra.y, ra.z, ra.w};
            float bv[4] = {rb.x, rb.y, rb.z, rb.w};
            #pragma unroll
            for (int i = 0; i < 4; i++)
                #pragma unroll
                for (int j = 0; j < 4; j++)
                    acc[i][j] += av[i] * bv[j];
        }
        __syncthreads();
    }
    #pragma unroll
    for (int i = 0; i < 4; i++) {
        int m = m0 + (ty << 2) + i;
        #pragma unroll
        for (int j = 0; j < 4; j++) {
            int n = n0 + (tx << 2) + j;
            C[(size_t)m * N + n] = acc[i][j] * scale;
        }
    }
}

// ---------------------------------------------------------------------------
// Top-k + softmax + sparse AV + full attn-row write (no separate zerofill)
// ---------------------------------------------------------------------------
__device__ __forceinline__ unsigned encf(float x) {
    unsigned u = __float_as_uint(x);
    return (u & 0x80000000u) ? ~u : (u | 0x80000000u);
}
__device__ __forceinline__ float decf(unsigned u) {
    return (u & 0x80000000u) ? __uint_as_float(u ^ 0x80000000u) : __uint_as_float(~u);
}
__device__ __forceinline__ int warp_incl_scan(int v, int lane) {
    #pragma unroll
    for (int o = 1; o < 32; o <<= 1) {
        int n = __shfl_up_sync(0xffffffffu, v, o);
        if (lane >= o) v += n;
    }
    return v;
}
__device__ __forceinline__ int ballot_append(bool flag, int* counter, int lane) {
    unsigned m = __ballot_sync(0xffffffffu, flag);
    int base = 0;
    if (m) {
        int leader = __ffs(m) - 1;
        if (lane == leader) base = atomicAdd(counter, __popc(m));
        base = __shfl_sync(0xffffffffu, base, leader);
    }
    return base + __popc(m & ((1u << lane) - 1u));
}
__device__ __forceinline__ void pick_digit(int* hist, int kk, int tid, int lane,
                                           int wid, int* wtot, int* s_d, int* s_k) {
    int h0 = hist[2*tid], h1 = hist[2*tid+1];
    int ps = h0 + h1;
    int incl = warp_incl_scan(ps, lane);
    if (lane == 31) wtot[wid] = incl;
    __syncthreads();
    int base = 0;
    #pragma unroll
    for (int w2 = 0; w2 < 4; w2++) if (w2 < wid) base += wtot[w2];
    int Tot = wtot[0] + wtot[1] + wtot[2] + wtot[3];
    int inclAll = incl + base;
    int S0 = Tot - inclAll + ps;
    int S1 = S0 - h0;
    int S2 = S0 - ps;
    if (S0 >= kk && S1 < kk) { *s_d = 2*tid;   *s_k = kk - S1; }
    if (S1 >= kk && S2 < kk) { *s_d = 2*tid+1; *s_k = kk - S2; }
    __syncthreads();
}

__global__ __launch_bounds__(128) void topk_attn_kernel(
    const float* __restrict__ logits, const float* __restrict__ vp,
    float* __restrict__ mix, float* __restrict__ attn, int write_attn)
{
    const int row = blockIdx.x;
    const int bh  = row >> 11;
    const int qi  = row & 2047;
    const int b   = bh >> 4;
    const int h   = bh & 15;
    const int tid = threadIdx.x;
    const int lane = tid & 31;
    const int wid  = tid >> 5;

    __shared__ unsigned su[LK_];
    __shared__ int      cand[LK_];
    __shared__ int      hist[256];
    __shared__ int      wtot[4];
    __shared__ unsigned wmax[4];
    __shared__ float    wsum[2];
    __shared__ int      sel_idx[TOPK_];
    __shared__ float    sel_w[TOPK_];
    __shared__ float    sred[128];
    __shared__ int      s_d, s_k, s_nsel, s_ncand;
    __shared__ float    s_max, s_invZ;

    // --- Load row, encode keys, rowmax ---
    const float4* lrow4 = (const float4*)(logits + (size_t)row * LK_);
    unsigned lm = 0u;
    #pragma unroll
    for (int it = 0; it < 4; it++) {
        int i4 = tid + it * 128;
        float4 x = lrow4[i4];
        unsigned e0 = encf(x.x), e1 = encf(x.y), e2 = encf(x.z), e3 = encf(x.w);
        su[4*i4+0] = e0; su[4*i4+1] = e1; su[4*i4+2] = e2; su[4*i4+3] = e3;
        unsigned m01 = e0 > e1 ? e0 : e1;
        unsigned m23 = e2 > e3 ? e2 : e3;
        unsigned m = m01 > m23 ? m01 : m23;
        lm = lm > m ? lm : m;
    }
    #pragma unroll
    for (int o = 16; o > 0; o >>= 1) {
        unsigned v = __shfl_xor_sync(0xffffffffu, lm, o);
        lm = lm > v ? lm : v;
    }
    if (lane == 0) wmax[wid] = lm;
    if (tid == 0) { s_nsel = 0; s_ncand = 0; }
    hist[tid] = 0; hist[tid + 128] = 0;
    __syncthreads();
    if (tid == 0) {
        unsigned m = wmax[0];
        m = m > wmax[1] ? m : wmax[1];
        m = m > wmax[2] ? m : wmax[2];
        m = m > wmax[3] ? m : wmax[3];
        s_max = decf(m);
    }

    // --- Pass 1: top-byte histogram over all 2048 ---
    #pragma unroll 4
    for (int it = 0; it < 16; it++) {
        unsigned u = su[tid + it * 128];
        int d = (int)(u >> 24);
        unsigned mm = __match_any_sync(0xffffffffu, d);
        if ((int)(__ffs(mm) - 1) == lane) atomicAdd(&hist[d], __popc(mm));
    }
    __syncthreads();
    pick_digit(hist, TOPK_, tid, lane, wid, wtot, &s_d, &s_k);
    const float rowmax = s_max;
    int d1 = s_d;
    int kk = s_k;

    // --- Compact boundary bin ---
    #pragma unroll
    for (int it = 0; it < 16; it++) {
        int i = tid + it * 128;
        unsigned dg = su[i] >> 24;
        bool is_g = (int)dg > d1;
        bool is_e = (int)dg == d1;
        int pg = ballot_append(is_g, &s_nsel, lane);
        if (is_g) sel_idx[pg] = i;
        int pe = ballot_append(is_e, &s_ncand, lane);
        if (is_e) cand[pe] = i;
    }
    __syncthreads();
    int C = s_ncand;

    // --- Passes 2..4 on shrinking candidate list ---
    for (int shift = 16; shift >= 0; shift -= 8) {
        if (C == kk) break;
        hist[tid] = 0; hist[tid + 128] = 0;
        __syncthreads();
        for (int c0 = 0; c0 < C; c0 += 128) {
            int c = c0 + tid;
            if (c < C) atomicAdd(&hist[(su[cand[c]] >> shift) & 255u], 1);
        }
        __syncthreads();
        pick_digit(hist, kk, tid, lane, wid, wtot, &s_d, &s_k);
        int d = s_d;
        int mine[16]; int nm = 0;
        for (int c0 = 0; c0 < C; c0 += 128) {
            int c = c0 + tid;
            if (c < C) mine[nm++] = cand[c];
        }
        __syncthreads();
        if (tid == 0) s_ncand = 0;
        __syncthreads();
        int Cpad = (C + 127) & ~127;
        int used = 0;
        for (int c0 = 0; c0 < Cpad; c0 += 128) {
            int c = c0 + tid;
            bool active = (c < C);
            int idx = active ? mine[used] : 0;
            if (active) used++;
            unsigned dg = active ? ((su[idx] >> shift) & 255u) : 0u;
            bool is_g = active && ((int)dg > d);
            bool is_e = active && ((int)dg == d);
            int pg = ballot_append(is_g, &s_nsel, lane);
            if (is_g) sel_idx[pg] = idx;
            int pe = ballot_append(is_e, &s_ncand, lane);
            if (is_e) cand[pe] = idx;
        }
        __syncthreads();
        C = s_ncand;
        kk = s_k;
    }

    // --- Finish (ties by lowest index, jax semantics) ---
    if (C == kk) {
        for (int c0 = 0; c0 < C; c0 += 128) {
            int c = c0 + tid;
            if (c < C) { int pos = atomicAdd(&s_nsel, 1); sel_idx[pos] = cand[c]; }
        }
    } else {
        for (int c0 = 0; c0 < C; c0 += 128) {
            int c = c0 + tid;
            if (c < C) {
                int idx = cand[c];
                int r = 0;
                for (int j = 0; j < C; j++) r += (cand[j] < idx);
                if (r < kk) { int pos = atomicAdd(&s_nsel, 1); sel_idx[pos] = idx; }
            }
        }
    }
    __syncthreads();

    // --- Softmax over the 64 selected ---
    float w = 0.f;
    if (tid < TOPK_) {
        w = expf(decf(su[sel_idx[tid]]) - rowmax);
        sel_w[tid] = w;
    }
    float zl = w;
    #pragma unroll
    for (int o = 16; o > 0; o >>= 1) zl += __shfl_xor_sync(0xffffffffu, zl, o);
    if (tid < TOPK_ && lane == 0) wsum[wid] = zl;
    __syncthreads();
    if (tid == 0) s_invZ = 1.0f / (wsum[0] + wsum[1]);
    __syncthreads();
    const float invZ = s_invZ;
    if (tid < TOPK_) sel_w[tid] = sel_w[tid] * invZ;
    __syncthreads();

    // --- Build full attn row in smem (reuse su) and stream out coalesced ---
    if (write_attn) {
        float4* s4 = (float4*)su;
        const float4 z4 = make_float4(0.f, 0.f, 0.f, 0.f);
        #pragma unroll
        for (int it = 0; it < 4; it++) s4[tid + it * 128] = z4;
        __syncthreads();
        if (tid < TOPK_) ((float*)su)[sel_idx[tid]] = sel_w[tid];
        __syncthreads();
        float4* arow4 = (float4*)(attn + (size_t)row * LK_);
        #pragma unroll
        for (int it = 0; it < 4; it++) arow4[tid + it * 128] = s4[tid + it * 128];
    }

    // --- Sparse AV ---
    {
        const int d = tid & 63, half = tid >> 6;
        const float* vb = vp + (size_t)bh * LK_ * 64;
        float accv = 0.f;
        for (int s = half; s < TOPK_; s += 2)
            accv += sel_w[s] * vb[(size_t)sel_idx[s] * 64 + d];
        sred[tid] = accv;
        __syncthreads();
        if (tid < 64)
            mix[((size_t)(b * LQ_ + qi)) * (HH * DVV) + h * 64 + tid] =
                sred[tid] + sred[tid + 64];
    }
}

// ---------------------------------------------------------------------------
extern "C" void kernel_launch(void* const* d_in, const int* in_sizes, int n_in,
                              void* d_out, int out_size) {
    (void)in_sizes; (void)n_in;
    const float* q    = (const float*)d_in[0];
    const float* k    = (const float*)d_in[1];
    const float* v    = (const float*)d_in[2];
    const float* w_qs = (const float*)d_in[3];
    const float* w_ks = (const float*)d_in[4];
    const float* w_vs = (const float*)d_in[5];
    const float* fc   = (const float*)d_in[6];
    float* out = (float*)d_out;

    float *qp, *kp, *vp, *mix, *lg;
    cudaGetSymbolAddress((void**)&qp,  g_qp);
    cudaGetSymbolAddress((void**)&kp,  g_kp);
    cudaGetSymbolAddress((void**)&vp,  g_vp);
    cudaGetSymbolAddress((void**)&mix, g_mix);
    cudaGetSymbolAddress((void**)&lg,  g_logits);

    const long long out_elems  = (long long)BB * LQ_ * DVV;           // 262144
    const long long attn_elems = (long long)BB * HH * LQ_ * LK_;      // 134217728
    int write_attn = ((long long)out_size >= out_elems + attn_elems) ? 1 : 0;
    float* attn = out + out_elems;

    dim3 blk(256);
    sgemm128<<<dim3(8, 32, 1), blk>>>(q, w_qs, qp, BB*LQ_, HH*DKK, EE, 0, 0.125f, LQ_, 0, 0, 0);
    sgemm128<<<dim3(8, 32, 1), blk>>>(k, w_ks, kp, BB*LK_, HH*DKK, EE, 0, 1.0f, LK_, 0, 0, 0);
    sgemm128<<<dim3(8, 32, 1), blk>>>(v, w_vs, vp, BB*LK_, HH*DVV, DVV, 0, 1.0f, LK_, 0, 0, 0);
    sgemm128<<<dim3(16, 16, BB*HH), blk>>>(qp, kp, lg, LQ_, LK_, DKK, 1, 1.0f, 0,
                                           (size_t)LQ_ * DKK, (size_t)LK_ * DKK,
                                           (size_t)LQ_ * LK_);

    topk_attn_kernel<<<BB * HH * LQ_, 128>>>(lg, vp, mix, attn, write_attn);

    sgemm_nt<<<dim3(1, 64, 1), blk>>>(mix, fc, out, BB*LQ_, DVV, HH*DVV, 1.0f);
}